// round 12
// baseline (speedup 1.0000x reference)
#include <cuda_runtime.h>
#include <cstdint>

#define N_  4
#define C_  128
#define H_  216
#define W_  384
#define HW_ (H_ * W_)          // 82944
#define NHW_ (N_ * HW_)        // 331776
#define TOTAL_ (N_ * C_ * HW_) // 42467328

// ---------------- scatter config ----------------
#define PAD 4
#define ROW (C_ + PAD)         // 132
#define WTILE 32
#define SCTAS (H_ * (W_ / WTILE))       // 2592 per batch

// ---------------- gather config ----------------
#define GT 128                 // pixels per gather tile
#define GCH 64                 // channels per gather CTA (half of C)
#define GPP 132                // padded pixel stride (floats) in smem
#define GCTAS (H_ * (W_ / GT) * 2)      // 1296 per batch (2 channel-halves)

// NHWC accumulation scratch (zeroed at module load; re-zeroed by gather each
// iteration so graph replays are deterministic).  o-scratch is duplicated so
// the two channel-half gather CTAs can independently read+zero their copy.
__device__ __align__(16) float g_scr[TOTAL_];
__device__ __align__(16) float g_oscr[2][NHW_];

__device__ __forceinline__ void red_add_v4(float* p, float a, float b, float c, float d) {
    asm volatile("red.global.add.v4.f32 [%0], {%1,%2,%3,%4};"
                 :: "l"(p), "f"(a), "f"(b), "f"(c), "f"(d) : "memory");
}
__device__ __forceinline__ void red_add_f32(float* p, float a) {
    asm volatile("red.global.add.f32 [%0], %1;" :: "l"(p), "f"(a) : "memory");
}

// ---------------------------------------------------------------------------
// Kernel 1: scatter for ONE batch n.  CTA = 32 consecutive w of one h row.
// ---------------------------------------------------------------------------
__global__ __launch_bounds__(256) void scatter_kernel(
    const float* __restrict__ img, const float* __restrict__ flo, const int n)
{
    __shared__ __align__(16) float tile[WTILE * ROW];

    const int bid  = blockIdx.x;
    const int h    = bid / (W_ / WTILE);
    const int w0   = (bid % (W_ / WTILE)) * WTILE;
    const int tid  = threadIdx.x;
    const int lane = tid & 31;
    const int warp = tid >> 5;

    const float* src = img + ((size_t)n * C_ * H_ + h) * (size_t)W_ + w0;
    #pragma unroll
    for (int cb = 0; cb < C_; cb += 8) {
        int c = cb + warp;
        tile[lane * ROW + c] = __ldcs(src + (size_t)c * HW_ + lane);
    }
    __syncthreads();

    const float* flo_y = flo + ((size_t)n * 2) * HW_ + h * W_ + w0;   // shifts W
    const float* flo_x = flo_y + HW_;                                  // shifts H
    float* const base_n = g_scr + (size_t)n * HW_ * C_;
    const size_t obase  = (size_t)n * HW_;

    #pragma unroll
    for (int i = 0; i < 4; i++) {
        const int p = warp * 4 + i;
        const int w = w0 + p;

        const float fy = __ldcs(flo_y + p);
        const float fx = __ldcs(flo_x + p);
        const float x1f = floorf(fx), y1f = floorf(fy);
        const float dx = fx - x1f, dy = fy - y1f;
        const int th0 = h + (int)x1f;
        const int tw0 = w + (int)y1f;

        const float ex0 = __expf(-dx * dx);
        const float ex1 = __expf(-(dx - 1.f) * (dx - 1.f));
        const float ey0 = __expf(-dy * dy);
        const float ey1 = __expf(-(dy - 1.f) * (dy - 1.f));

        const float4 v = *(const float4*)&tile[p * ROW + lane * 4];

        #pragma unroll
        for (int ci = 0; ci < 2; ci++) {
            const int th = th0 + ci;
            if (th < 0 || th >= H_) continue;
            const float exi = ci ? ex1 : ex0;
            #pragma unroll
            for (int cj = 0; cj < 2; cj++) {
                const int tw = tw0 + cj;
                if (tw < 0 || tw >= W_) continue;
                const float wt = exi * (cj ? ey1 : ey0);
                float* dst = base_n + ((size_t)th * W_ + tw) * C_ + lane * 4;
                red_add_v4(dst, v.x * wt, v.y * wt, v.z * wt, v.w * wt);
                if (lane < 2)   // dual o-scratch: lane k feeds copy k
                    red_add_f32(&g_oscr[lane][obase + th * W_ + tw], wt);
            }
        }
    }
}

// ---------------------------------------------------------------------------
// Kernel 2: gather for ONE batch n, ONE 64-channel half.
// grid = 1296: bid bit0 = channel half, rest = (h, w0).  34KB static smem,
// ~40 regs -> 3 CTAs/SM (75% occ).  Each half reads+zeroes its own o copy.
//   Phase A: 4 independent ld.cs float4 (MLP=4) + st.cs zeros + swizzled STS.
//   Phase B: swizzled LDS.128 self-deswizzles; plain lane*4 global offsets.
// ---------------------------------------------------------------------------
__global__ __launch_bounds__(512, 3) void gather_kernel(float* __restrict__ out,
                                                        const int n)
{
    __shared__ __align__(16) float tile[GCH * GPP];   // 33792 B
    __shared__ __align__(16) float ovs[GT];           // 512 B

    const int bid  = blockIdx.x;
    const int half = bid & 1;
    const int rest = bid >> 1;
    const int h    = rest / (W_ / GT);
    const int w0   = (rest % (W_ / GT)) * GT;
    const int tid  = threadIdx.x;
    const int lane = tid & 31;
    const int warp = tid >> 5;

    const size_t pixbase = (size_t)n * HW_ + (size_t)h * W_ + w0;
    float4* const scr4 = (float4*)(g_scr + pixbase * C_);   // 128 pix * 32 quads

    float* const out_img_base = out + ((size_t)n * C_ * H_ + h) * (size_t)W_ + w0
                              + (size_t)half * GCH * HW_;
    float* const out_o_base   = out_img_base + (size_t)TOTAL_;

    // ---- phase A: 4 independent streaming loads (this half's 16 quads) ----
    float4 v[4];
    int   off[4];
    #pragma unroll
    for (int it = 0; it < 4; it++) {
        const int idx = it * 512 + tid;                 // 0..2047
        const int p   = idx >> 4;                       // pixel 0..127
        const int q   = idx & 15;                       // quad within half
        off[it] = p * 32 + half * 16 + q;
        v[it]   = __ldcs(scr4 + off[it]);
    }
    const float4 z4 = make_float4(0.f, 0.f, 0.f, 0.f);
    #pragma unroll
    for (int it = 0; it < 4; it++)
        __stcs(scr4 + off[it], z4);

    // this half's private o copy: read + zero
    if (tid < GT) {
        ovs[tid] = __ldcs(&g_oscr[half][pixbase + tid]);
        __stcs(&g_oscr[half][pixbase + tid], 0.f);
    }

    // transpose into smem with XOR column swizzle (q = quad within half)
    #pragma unroll
    for (int it = 0; it < 4; it++) {
        const int p  = off[it] >> 5;
        const int q  = (off[it] & 31) - half * 16;      // 0..15
        const int ps = p ^ ((q & 7) << 2);
        const int c0 = q * 4;                           // channel within half
        tile[(c0 + 0) * GPP + ps] = v[it].x;
        tile[(c0 + 1) * GPP + ps] = v[it].y;
        tile[(c0 + 2) * GPP + ps] = v[it].z;
        tile[(c0 + 3) * GPP + ps] = v[it].w;
    }
    __syncthreads();

    // ---- phase B: 4 channel-visits per warp, 512B contiguous stores ----
    #pragma unroll
    for (int cb = 0; cb < 4; cb++) {
        const int cl  = cb * 16 + warp;                 // channel within half
        const int qc  = cl >> 2;
        const int psw = (lane * 4) ^ ((qc & 7) << 2);   // swizzled smem index
        const float4 vv = *(const float4*)&tile[cl * GPP + psw];
        const float4 ov = *(const float4*)&ovs[lane * 4];
        __stcs((float4*)(out_img_base + (size_t)cl * HW_ + lane * 4), vv);
        __stcs((float4*)(out_o_base   + (size_t)cl * HW_ + lane * 4), ov);
    }
}

extern "C" void kernel_launch(void* const* d_in, const int* in_sizes, int n_in,
                              void* d_out, int out_size)
{
    const float* img;
    const float* flo;
    if (in_sizes[0] == TOTAL_) { img = (const float*)d_in[0]; flo = (const float*)d_in[1]; }
    else                       { img = (const float*)d_in[1]; flo = (const float*)d_in[0]; }
    float* out = (float*)d_out;

    // One-time setup (uncaptured correctness call): EXACTLY R10's resource
    // footprint — 1 extra stream + 5 events — which passed graph teardown.
    static cudaStream_t s1 = nullptr;
    static cudaEvent_t  evS[N_], evJoin;
    if (s1 == nullptr) {
        cudaStreamCreateWithFlags(&s1, cudaStreamNonBlocking);
        for (int i = 0; i < N_; i++)
            cudaEventCreateWithFlags(&evS[i], cudaEventDisableTiming);
        cudaEventCreateWithFlags(&evJoin, cudaEventDisableTiming);
    }

    // Scatters back-to-back on the capture stream; gathers forked onto s1
    // (G_n waits only on S_n).  Join before return.
    for (int n = 0; n < N_; n++) {
        scatter_kernel<<<SCTAS, 256>>>(img, flo, n);
        cudaEventRecord(evS[n], 0);
        cudaStreamWaitEvent(s1, evS[n], 0);
        gather_kernel<<<GCTAS, 512, 0, s1>>>(out, n);
    }
    cudaEventRecord(evJoin, s1);
    cudaStreamWaitEvent(0, evJoin, 0);
}

// round 13
// speedup vs baseline: 1.0362x; 1.0362x over previous
#include <cuda_runtime.h>
#include <cstdint>

#define N_  4
#define C_  128
#define H_  216
#define W_  384
#define HW_ (H_ * W_)          // 82944
#define NHW_ (N_ * HW_)        // 331776
#define TOTAL_ (N_ * C_ * HW_) // 42467328

#define HHALF (H_ / 2)         // 108 rows per pipeline stage

// ---------------- scatter config ----------------
#define PAD 4
#define ROW (C_ + PAD)         // 132
#define WTILE 32
#define SCTAS (HHALF * (W_ / WTILE))    // 1296 per half-batch

// ---------------- gather config (R10-proven) ----------------
#define GT 128                 // pixels per gather tile
#define GPP 132                // padded pixel stride (floats) in smem, c-major
#define GCTAS (HHALF * (W_ / GT))       // 324 per half-batch
#define GSMEM (C_ * GPP * 4 + GT * 4)   // 68096 B

// NHWC accumulation scratch (zeroed at module load; re-zeroed by gather each
// iteration so graph replays are deterministic).
__device__ __align__(16) float g_scr[TOTAL_];
__device__ __align__(16) float g_oscr[NHW_];

__device__ __forceinline__ void red_add_v4(float* p, float a, float b, float c, float d) {
    asm volatile("red.global.add.v4.f32 [%0], {%1,%2,%3,%4};"
                 :: "l"(p), "f"(a), "f"(b), "f"(c), "f"(d) : "memory");
}
__device__ __forceinline__ void red_add_f32(float* p, float a) {
    asm volatile("red.global.add.f32 [%0], %1;" :: "l"(p), "f"(a) : "memory");
}

// ---------------------------------------------------------------------------
// Kernel 1: scatter for ONE half of batch n (h in [h0, h0+108)).
// CTA = 32 consecutive w of one h row.
// ---------------------------------------------------------------------------
__global__ __launch_bounds__(256) void scatter_kernel(
    const float* __restrict__ img, const float* __restrict__ flo,
    const int n, const int h0)
{
    __shared__ __align__(16) float tile[WTILE * ROW];

    const int bid  = blockIdx.x;
    const int h    = h0 + bid / (W_ / WTILE);
    const int w0   = (bid % (W_ / WTILE)) * WTILE;
    const int tid  = threadIdx.x;
    const int lane = tid & 31;
    const int warp = tid >> 5;

    const float* src = img + ((size_t)n * C_ * H_ + h) * (size_t)W_ + w0;
    #pragma unroll
    for (int cb = 0; cb < C_; cb += 8) {
        int c = cb + warp;
        tile[lane * ROW + c] = __ldcs(src + (size_t)c * HW_ + lane);
    }
    __syncthreads();

    const float* flo_y = flo + ((size_t)n * 2) * HW_ + h * W_ + w0;   // shifts W
    const float* flo_x = flo_y + HW_;                                  // shifts H
    float* const base_n = g_scr + (size_t)n * HW_ * C_;
    float* const obase  = g_oscr + (size_t)n * HW_;

    #pragma unroll
    for (int i = 0; i < 4; i++) {
        const int p = warp * 4 + i;
        const int w = w0 + p;

        const float fy = __ldcs(flo_y + p);
        const float fx = __ldcs(flo_x + p);
        const float x1f = floorf(fx), y1f = floorf(fy);
        const float dx = fx - x1f, dy = fy - y1f;
        const int th0 = h + (int)x1f;
        const int tw0 = w + (int)y1f;

        const float ex0 = __expf(-dx * dx);
        const float ex1 = __expf(-(dx - 1.f) * (dx - 1.f));
        const float ey0 = __expf(-dy * dy);
        const float ey1 = __expf(-(dy - 1.f) * (dy - 1.f));

        const float4 v = *(const float4*)&tile[p * ROW + lane * 4];

        #pragma unroll
        for (int ci = 0; ci < 2; ci++) {
            const int th = th0 + ci;
            if (th < 0 || th >= H_) continue;
            const float exi = ci ? ex1 : ex0;
            #pragma unroll
            for (int cj = 0; cj < 2; cj++) {
                const int tw = tw0 + cj;
                if (tw < 0 || tw >= W_) continue;
                const float wt = exi * (cj ? ey1 : ey0);
                float* dst = base_n + ((size_t)th * W_ + tw) * C_ + lane * 4;
                red_add_v4(dst, v.x * wt, v.y * wt, v.z * wt, v.w * wt);
                if (lane == 0)
                    red_add_f32(obase + th * W_ + tw, wt);
            }
        }
    }
}

// NOTE on scatter->gather dependency across halves: a scatter with h in
// [0,108) can write targets up to h ~ 118 (flows ~N(0,8)); the gather for a
// half therefore waits on BOTH halves' scatters of its batch (see DAG below)
// -- implemented by forking the gather only after the second scatter event
// for halves that need it.  Simpler and correct: gather half k of batch n
// waits on scatter half k AND the other half's scatter, i.e. on S_{n,1}
// completion for both.  To keep overlap, gather half 0 waits only on S_{n,0}
// if flows cannot cross the h0=108 boundary... they CAN.  So both gather
// halves wait on S_{n,1}.  Overlap is preserved because S_{n+1,*} proceeds
// on stream 0 while gathers of batch n run on s1.

// ---------------------------------------------------------------------------
// Kernel 2: gather for ONE half of batch n (R10-proven config).
//   Phase A: 8 INDEPENDENT ld.cs float4 (MLP=8), then 8 st.cs zeros, then
//            transpose into c-major smem with XOR column swizzle (2-way STS).
//   Phase B: swizzled LDS.128 self-deswizzles; plain lane*4 global offsets.
// ---------------------------------------------------------------------------
__global__ __launch_bounds__(512, 2) void gather_kernel(float* __restrict__ out,
                                                        const int n, const int h0)
{
    extern __shared__ __align__(16) float smem[];
    float* const tile = smem;                 // [C_][GPP]
    float* const ovs  = smem + C_ * GPP;      // [GT]

    const int bid  = blockIdx.x;
    const int h    = h0 + bid / (W_ / GT);
    const int w0   = (bid % (W_ / GT)) * GT;
    const int tid  = threadIdx.x;
    const int lane = tid & 31;
    const int warp = tid >> 5;

    const size_t pixbase = (size_t)n * HW_ + (size_t)h * W_ + w0;
    float4* const scr4 = (float4*)(g_scr + pixbase * C_);   // 128 pix * 32 quads

    float* const out_img_base = out + ((size_t)n * C_ * H_ + h) * (size_t)W_ + w0;
    float* const out_o_base   = out_img_base + (size_t)TOTAL_;

    // ---- phase A: 8 independent streaming loads ----
    float4 v[8];
    int   off[8];
    #pragma unroll
    for (int it = 0; it < 8; it++) {
        const int idx = it * 512 + tid;                     // 0..4095
        const int p   = (idx >> 4) & 127;                   // pixel
        const int q   = ((idx >> 11) << 4) | (idx & 15);    // channel quad 0..31
        off[it] = p * 32 + q;
        v[it]   = __ldcs(scr4 + off[it]);
    }
    const float4 z4 = make_float4(0.f, 0.f, 0.f, 0.f);
    #pragma unroll
    for (int it = 0; it < 8; it++)
        __stcs(scr4 + off[it], z4);

    if (tid < GT) {
        ovs[tid] = __ldcs(g_oscr + pixbase + tid);
        __stcs(g_oscr + pixbase + tid, 0.f);
    }

    #pragma unroll
    for (int it = 0; it < 8; it++) {
        const int p  = off[it] >> 5;
        const int q  = off[it] & 31;
        const int ps = p ^ ((q & 7) << 2);
        const int c0 = q * 4;
        tile[(c0 + 0) * GPP + ps] = v[it].x;
        tile[(c0 + 1) * GPP + ps] = v[it].y;
        tile[(c0 + 2) * GPP + ps] = v[it].z;
        tile[(c0 + 3) * GPP + ps] = v[it].w;
    }
    __syncthreads();

    // ---- phase B: 8 channel-visits per warp, 512B contiguous stores ----
    #pragma unroll
    for (int cb = 0; cb < 8; cb++) {
        const int cl  = cb * 16 + warp;                    // channel 0..127
        const int qc  = cl >> 2;
        const int psw = (lane * 4) ^ ((qc & 7) << 2);      // swizzled smem index
        const float4 vv = *(const float4*)&tile[cl * GPP + psw];
        const float4 ov = *(const float4*)&ovs[lane * 4];
        __stcs((float4*)(out_img_base + (size_t)cl * HW_ + lane * 4), vv);
        __stcs((float4*)(out_o_base   + (size_t)cl * HW_ + lane * 4), ov);
    }
}

extern "C" void kernel_launch(void* const* d_in, const int* in_sizes, int n_in,
                              void* d_out, int out_size)
{
    const float* img;
    const float* flo;
    if (in_sizes[0] == TOTAL_) { img = (const float*)d_in[0]; flo = (const float*)d_in[1]; }
    else                       { img = (const float*)d_in[1]; flo = (const float*)d_in[0]; }
    float* out = (float*)d_out;

    // One-time setup (uncaptured correctness call): 1 extra stream + events,
    // the teardown-proven footprint shape from R10.
    static cudaStream_t s1 = nullptr;
    static cudaEvent_t  evS[N_], evJoin;
    if (s1 == nullptr) {
        cudaStreamCreateWithFlags(&s1, cudaStreamNonBlocking);
        for (int i = 0; i < N_; i++)
            cudaEventCreateWithFlags(&evS[i], cudaEventDisableTiming);
        cudaEventCreateWithFlags(&evJoin, cudaEventDisableTiming);
        cudaFuncSetAttribute(gather_kernel,
                             cudaFuncAttributeMaxDynamicSharedMemorySize, GSMEM);
    }

    // Pipeline: both half-scatters of batch n on stream 0 (flows can cross
    // the half boundary, so gathers of batch n depend on BOTH), then the two
    // half-gathers fork onto s1.  The half-grain shrinks the final tail to a
    // half-batch gather and smooths contention.
    for (int n = 0; n < N_; n++) {
        scatter_kernel<<<SCTAS, 256>>>(img, flo, n, 0);
        scatter_kernel<<<SCTAS, 256>>>(img, flo, n, HHALF);
        cudaEventRecord(evS[n], 0);
        cudaStreamWaitEvent(s1, evS[n], 0);
        gather_kernel<<<GCTAS, 512, GSMEM, s1>>>(out, n, 0);
        gather_kernel<<<GCTAS, 512, GSMEM, s1>>>(out, n, HHALF);
    }
    cudaEventRecord(evJoin, s1);
    cudaStreamWaitEvent(0, evJoin, 0);
}

// round 14
// speedup vs baseline: 1.4998x; 1.4475x over previous
#include <cuda_runtime.h>
#include <cuda_fp16.h>
#include <cstdint>

#define N_  4
#define C_  128
#define H_  216
#define W_  384
#define HW_ (H_ * W_)          // 82944
#define NHW_ (N_ * HW_)        // 331776
#define TOTAL_ (N_ * C_ * HW_) // 42467328

// ---------------- scatter config ----------------
#define PAD 4
#define ROW (C_ + PAD)         // 132
#define WTILE 32
#define SCTAS (H_ * (W_ / WTILE))       // 2592 per batch

// ---------------- gather config ----------------
#define GT 128                 // pixels per gather tile
#define GPP 132                // padded pixel stride (floats) in smem, c-major
#define GCTAS (H_ * (W_ / GT))          // 648 per batch
#define GSMEM (C_ * GPP * 4 + GT * 4)   // 68096 B

// NHWC fp16 accumulation scratch (zeroed at module load; re-zeroed by gather
// each iteration).  o-scratch stays fp32 (tiny, positive sums).
__device__ __align__(16) __half g_scr[TOTAL_];
__device__ __align__(16) float  g_oscr[NHW_];

__device__ __forceinline__ void red_add_v4h2(__half* p, uint32_t a, uint32_t b,
                                             uint32_t c, uint32_t d) {
    asm volatile("red.global.add.noftz.v4.f16x2 [%0], {%1,%2,%3,%4};"
                 :: "l"(p), "r"(a), "r"(b), "r"(c), "r"(d) : "memory");
}
__device__ __forceinline__ void red_add_f32(float* p, float a) {
    asm volatile("red.global.add.f32 [%0], %1;" :: "l"(p), "f"(a) : "memory");
}
__device__ __forceinline__ uint32_t h2u(__half2 h) {
    return *reinterpret_cast<uint32_t*>(&h);
}

// ---------------------------------------------------------------------------
// Kernel 1: scatter for ONE batch n.  CTA = 32 consecutive w of one h row.
// Each warp iteration handles TWO pixels: lanes 0-15 -> pixel A, 16-31 -> B.
// Lane owns an 8-channel octet; one red.v4.f16x2 (16B) per corner per lane.
// ---------------------------------------------------------------------------
__global__ __launch_bounds__(256) void scatter_kernel(
    const float* __restrict__ img, const float* __restrict__ flo, const int n)
{
    __shared__ __align__(16) float tile[WTILE * ROW];

    const int bid  = blockIdx.x;
    const int h    = bid / (W_ / WTILE);
    const int w0   = (bid % (W_ / WTILE)) * WTILE;
    const int tid  = threadIdx.x;
    const int lane = tid & 31;
    const int warp = tid >> 5;
    const int sub  = lane >> 4;          // 0/1: which pixel of the pair
    const int q    = lane & 15;          // channel octet 0..15

    const float* src = img + ((size_t)n * C_ * H_ + h) * (size_t)W_ + w0;
    #pragma unroll
    for (int cb = 0; cb < C_; cb += 8) {
        int c = cb + warp;
        tile[lane * ROW + c] = __ldcs(src + (size_t)c * HW_ + lane);
    }
    __syncthreads();

    const float* flo_y = flo + ((size_t)n * 2) * HW_ + h * W_ + w0;   // shifts W
    const float* flo_x = flo_y + HW_;                                  // shifts H
    __half* const base_n = g_scr + (size_t)n * HW_ * C_;
    float* const  obase  = g_oscr + (size_t)n * HW_;

    #pragma unroll
    for (int i = 0; i < 2; i++) {
        const int p = warp * 4 + i * 2 + sub;
        const int w = w0 + p;

        const float fy = __ldcs(flo_y + p);
        const float fx = __ldcs(flo_x + p);
        const float x1f = floorf(fx), y1f = floorf(fy);
        const float dx = fx - x1f, dy = fy - y1f;
        const int th0 = h + (int)x1f;
        const int tw0 = w + (int)y1f;

        const float ex0 = __expf(-dx * dx);
        const float ex1 = __expf(-(dx - 1.f) * (dx - 1.f));
        const float ey0 = __expf(-dy * dy);
        const float ey1 = __expf(-(dy - 1.f) * (dy - 1.f));

        // this lane's 8 channels of pixel p, converted to 4x half2 once
        const float4 a = *(const float4*)&tile[p * ROW + 8 * q];
        const float4 b = *(const float4*)&tile[p * ROW + 8 * q + 4];
        const uint32_t v0 = h2u(__floats2half2_rn(a.x, a.y));
        const uint32_t v1 = h2u(__floats2half2_rn(a.z, a.w));
        const uint32_t v2 = h2u(__floats2half2_rn(b.x, b.y));
        const uint32_t v3 = h2u(__floats2half2_rn(b.z, b.w));

        #pragma unroll
        for (int ci = 0; ci < 2; ci++) {
            const int th = th0 + ci;
            if (th < 0 || th >= H_) continue;
            const float exi = ci ? ex1 : ex0;
            #pragma unroll
            for (int cj = 0; cj < 2; cj++) {
                const int tw = tw0 + cj;
                if (tw < 0 || tw >= W_) continue;
                const float wt = exi * (cj ? ey1 : ey0);
                const __half2 wh = __float2half2_rn(wt);
                __half* dst = base_n + ((size_t)th * W_ + tw) * C_ + 8 * q;
                red_add_v4h2(dst,
                             h2u(__hmul2(*(const __half2*)&v0, wh)),
                             h2u(__hmul2(*(const __half2*)&v1, wh)),
                             h2u(__hmul2(*(const __half2*)&v2, wh)),
                             h2u(__hmul2(*(const __half2*)&v3, wh)));
                if (q == 0)   // one lane per pixel (lane 0 and lane 16)
                    red_add_f32(obase + th * W_ + tw, wt);
            }
        }
    }
}

// ---------------------------------------------------------------------------
// Kernel 2: gather for ONE batch n (forked stream; R10-proven shape).
//   Phase A: 4 independent 16B ld.cs (8 halves each), st.cs zeros, convert
//            half2->fp32 into c-major smem with XOR column swizzle.
//   Phase B: swizzled LDS.128 self-deswizzles; plain lane*4 global offsets.
// ---------------------------------------------------------------------------
__global__ __launch_bounds__(512, 2) void gather_kernel(float* __restrict__ out,
                                                        const int n)
{
    extern __shared__ __align__(16) float smem[];
    float* const tile = smem;                 // [C_][GPP]
    float* const ovs  = smem + C_ * GPP;      // [GT]

    const int bid  = blockIdx.x;
    const int h    = bid / (W_ / GT);
    const int w0   = (bid % (W_ / GT)) * GT;
    const int tid  = threadIdx.x;
    const int lane = tid & 31;
    const int warp = tid >> 5;

    const size_t pixbase = (size_t)n * HW_ + (size_t)h * W_ + w0;
    uint4* const scr16 = (uint4*)(g_scr + pixbase * C_);  // 128 px * 16 octets

    float* const out_img_base = out + ((size_t)n * C_ * H_ + h) * (size_t)W_ + w0;
    float* const out_o_base   = out_img_base + (size_t)TOTAL_;

    // ---- phase A: 4 independent streaming loads (16B = 8 channels each) ----
    uint4 v[4];
    int  off[4];
    #pragma unroll
    for (int it = 0; it < 4; it++) {
        const int idx = it * 512 + tid;      // 0..2047
        const int p   = idx >> 4;            // pixel 0..127
        const int q   = idx & 15;            // channel octet 0..15
        off[it] = p * 16 + q;
        v[it]   = __ldcs(scr16 + off[it]);
    }
    const uint4 z16 = make_uint4(0, 0, 0, 0);
    #pragma unroll
    for (int it = 0; it < 4; it++)
        __stcs(scr16 + off[it], z16);

    if (tid < GT) {
        ovs[tid] = __ldcs(g_oscr + pixbase + tid);
        __stcs(g_oscr + pixbase + tid, 0.f);
    }

    // convert + transpose: tile[c][ p ^ ((q&7)<<2) ], c = 8q..8q+7
    #pragma unroll
    for (int it = 0; it < 4; it++) {
        const int p  = off[it] >> 4;
        const int q  = off[it] & 15;
        const int ps = p ^ ((q & 7) << 2);
        const int c0 = q * 8;
        const float2 f0 = __half22float2(*(const __half2*)&v[it].x);
        const float2 f1 = __half22float2(*(const __half2*)&v[it].y);
        const float2 f2 = __half22float2(*(const __half2*)&v[it].z);
        const float2 f3 = __half22float2(*(const __half2*)&v[it].w);
        tile[(c0 + 0) * GPP + ps] = f0.x;
        tile[(c0 + 1) * GPP + ps] = f0.y;
        tile[(c0 + 2) * GPP + ps] = f1.x;
        tile[(c0 + 3) * GPP + ps] = f1.y;
        tile[(c0 + 4) * GPP + ps] = f2.x;
        tile[(c0 + 5) * GPP + ps] = f2.y;
        tile[(c0 + 6) * GPP + ps] = f3.x;
        tile[(c0 + 7) * GPP + ps] = f3.y;
    }
    __syncthreads();

    // ---- phase B: 8 channel-visits per warp, 512B contiguous stores ----
    #pragma unroll
    for (int cb = 0; cb < 8; cb++) {
        const int cl  = cb * 16 + warp;                     // channel 0..127
        const int psw = (lane * 4) ^ (((cl >> 3) & 7) << 2); // swizzle of c's octet
        const float4 vv = *(const float4*)&tile[cl * GPP + psw];
        const float4 ov = *(const float4*)&ovs[lane * 4];
        __stcs((float4*)(out_img_base + (size_t)cl * HW_ + lane * 4), vv);
        __stcs((float4*)(out_o_base   + (size_t)cl * HW_ + lane * 4), ov);
    }
}

extern "C" void kernel_launch(void* const* d_in, const int* in_sizes, int n_in,
                              void* d_out, int out_size)
{
    const float* img;
    const float* flo;
    if (in_sizes[0] == TOTAL_) { img = (const float*)d_in[0]; flo = (const float*)d_in[1]; }
    else                       { img = (const float*)d_in[1]; flo = (const float*)d_in[0]; }
    float* out = (float*)d_out;

    // One-time setup (uncaptured correctness call): R10's teardown-proven
    // footprint — 1 extra stream + 5 events.
    static cudaStream_t s1 = nullptr;
    static cudaEvent_t  evS[N_], evJoin;
    if (s1 == nullptr) {
        cudaStreamCreateWithFlags(&s1, cudaStreamNonBlocking);
        for (int i = 0; i < N_; i++)
            cudaEventCreateWithFlags(&evS[i], cudaEventDisableTiming);
        cudaEventCreateWithFlags(&evJoin, cudaEventDisableTiming);
        cudaFuncSetAttribute(gather_kernel,
                             cudaFuncAttributeMaxDynamicSharedMemorySize, GSMEM);
    }

    // R10 DAG: scatters back-to-back on stream 0; gathers forked onto s1
    // (G_n waits only on S_n).  Join before return.
    for (int n = 0; n < N_; n++) {
        scatter_kernel<<<SCTAS, 256>>>(img, flo, n);
        cudaEventRecord(evS[n], 0);
        cudaStreamWaitEvent(s1, evS[n], 0);
        gather_kernel<<<GCTAS, 512, GSMEM, s1>>>(out, n);
    }
    cudaEventRecord(evJoin, s1);
    cudaStreamWaitEvent(0, evJoin, 0);
}

// round 15
// speedup vs baseline: 1.6216x; 1.0812x over previous
#include <cuda_runtime.h>
#include <cuda_fp16.h>
#include <cstdint>

#define N_  4
#define C_  128
#define H_  216
#define W_  384
#define HW_ (H_ * W_)          // 82944
#define NHW_ (N_ * HW_)        // 331776
#define TOTAL_ (N_ * C_ * HW_) // 42467328

// ---------------- scatter config ----------------
#define PAD 4
#define ROW (C_ + PAD)         // 132
#define WTILE 32
#define SCTAS (H_ * (W_ / WTILE))       // 2592 per batch

// ---------------- gather config ----------------
#define GT 128                 // pixels per gather tile
#define GPP 132                // padded pixel stride (floats) in smem, c-major
#define GCTAS (H_ * (W_ / GT))          // 648 per batch
#define GSMEM (C_ * GPP * 4 + GT * 4)   // 68096 B

// NHWC fp16 accumulation scratch (zeroed at module load; re-zeroed by gather
// each iteration).  o-scratch stays fp32 (tiny, positive sums).
__device__ __align__(16) __half g_scr[TOTAL_];
__device__ __align__(16) float  g_oscr[NHW_];

__device__ __forceinline__ void red_add_v4h2(__half* p, uint32_t a, uint32_t b,
                                             uint32_t c, uint32_t d) {
    asm volatile("red.global.add.noftz.v4.f16x2 [%0], {%1,%2,%3,%4};"
                 :: "l"(p), "r"(a), "r"(b), "r"(c), "r"(d) : "memory");
}
__device__ __forceinline__ void red_add_f32(float* p, float a) {
    asm volatile("red.global.add.f32 [%0], %1;" :: "l"(p), "f"(a) : "memory");
}
__device__ __forceinline__ uint32_t h2u(__half2 h) {
    return *reinterpret_cast<uint32_t*>(&h);
}

// ---------------------------------------------------------------------------
// Kernel 1: scatter for ONE batch n (unchanged from R14).
// Each warp iteration handles TWO pixels: lanes 0-15 -> pixel A, 16-31 -> B.
// Lane owns an 8-channel octet; one red.v4.f16x2 (16B) per corner per lane.
// ---------------------------------------------------------------------------
__global__ __launch_bounds__(256) void scatter_kernel(
    const float* __restrict__ img, const float* __restrict__ flo, const int n)
{
    __shared__ __align__(16) float tile[WTILE * ROW];

    const int bid  = blockIdx.x;
    const int h    = bid / (W_ / WTILE);
    const int w0   = (bid % (W_ / WTILE)) * WTILE;
    const int tid  = threadIdx.x;
    const int lane = tid & 31;
    const int warp = tid >> 5;
    const int sub  = lane >> 4;          // 0/1: which pixel of the pair
    const int q    = lane & 15;          // channel octet 0..15

    const float* src = img + ((size_t)n * C_ * H_ + h) * (size_t)W_ + w0;
    #pragma unroll
    for (int cb = 0; cb < C_; cb += 8) {
        int c = cb + warp;
        tile[lane * ROW + c] = __ldcs(src + (size_t)c * HW_ + lane);
    }
    __syncthreads();

    const float* flo_y = flo + ((size_t)n * 2) * HW_ + h * W_ + w0;   // shifts W
    const float* flo_x = flo_y + HW_;                                  // shifts H
    __half* const base_n = g_scr + (size_t)n * HW_ * C_;
    float* const  obase  = g_oscr + (size_t)n * HW_;

    #pragma unroll
    for (int i = 0; i < 2; i++) {
        const int p = warp * 4 + i * 2 + sub;
        const int w = w0 + p;

        const float fy = __ldcs(flo_y + p);
        const float fx = __ldcs(flo_x + p);
        const float x1f = floorf(fx), y1f = floorf(fy);
        const float dx = fx - x1f, dy = fy - y1f;
        const int th0 = h + (int)x1f;
        const int tw0 = w + (int)y1f;

        const float ex0 = __expf(-dx * dx);
        const float ex1 = __expf(-(dx - 1.f) * (dx - 1.f));
        const float ey0 = __expf(-dy * dy);
        const float ey1 = __expf(-(dy - 1.f) * (dy - 1.f));

        // this lane's 8 channels of pixel p, converted to 4x half2 once
        const float4 a = *(const float4*)&tile[p * ROW + 8 * q];
        const float4 b = *(const float4*)&tile[p * ROW + 8 * q + 4];
        const uint32_t v0 = h2u(__floats2half2_rn(a.x, a.y));
        const uint32_t v1 = h2u(__floats2half2_rn(a.z, a.w));
        const uint32_t v2 = h2u(__floats2half2_rn(b.x, b.y));
        const uint32_t v3 = h2u(__floats2half2_rn(b.z, b.w));

        #pragma unroll
        for (int ci = 0; ci < 2; ci++) {
            const int th = th0 + ci;
            if (th < 0 || th >= H_) continue;
            const float exi = ci ? ex1 : ex0;
            #pragma unroll
            for (int cj = 0; cj < 2; cj++) {
                const int tw = tw0 + cj;
                if (tw < 0 || tw >= W_) continue;
                const float wt = exi * (cj ? ey1 : ey0);
                const __half2 wh = __float2half2_rn(wt);
                __half* dst = base_n + ((size_t)th * W_ + tw) * C_ + 8 * q;
                red_add_v4h2(dst,
                             h2u(__hmul2(*(const __half2*)&v0, wh)),
                             h2u(__hmul2(*(const __half2*)&v1, wh)),
                             h2u(__hmul2(*(const __half2*)&v2, wh)),
                             h2u(__hmul2(*(const __half2*)&v3, wh)));
                if (q == 0)   // one lane per pixel (lane 0 and lane 16)
                    red_add_f32(obase + th * W_ + tw, wt);
            }
        }
    }
}

// ---------------------------------------------------------------------------
// Kernel 2: gather for ONE batch n.  256 threads, 8 INDEPENDENT 16B ld.cs
// per thread (MLP=8, ~98KB/SM outstanding at 3 CTAs/SM).
//   Phase A: 8 ld.cs -> 8 st.cs zeros -> half2->fp32 convert + swizzled STS.
//   Phase B: 16 channel-visits per warp; swizzled LDS.128 self-deswizzles;
//            plain lane*4 global offsets (512B contiguous per store).
// ---------------------------------------------------------------------------
__global__ __launch_bounds__(256, 3) void gather_kernel(float* __restrict__ out,
                                                        const int n)
{
    extern __shared__ __align__(16) float smem[];
    float* const tile = smem;                 // [C_][GPP]
    float* const ovs  = smem + C_ * GPP;      // [GT]

    const int bid  = blockIdx.x;
    const int h    = bid / (W_ / GT);
    const int w0   = (bid % (W_ / GT)) * GT;
    const int tid  = threadIdx.x;
    const int lane = tid & 31;
    const int warp = tid >> 5;                // 0..7

    const size_t pixbase = (size_t)n * HW_ + (size_t)h * W_ + w0;
    uint4* const scr16 = (uint4*)(g_scr + pixbase * C_);  // 128 px * 16 octets

    float* const out_img_base = out + ((size_t)n * C_ * H_ + h) * (size_t)W_ + w0;
    float* const out_o_base   = out_img_base + (size_t)TOTAL_;

    // ---- phase A: 8 independent streaming loads (16B = 8 channels each) ----
    uint4 v[8];
    int  off[8];
    #pragma unroll
    for (int it = 0; it < 8; it++) {
        const int idx = it * 256 + tid;      // 0..2047
        const int p   = idx >> 4;            // pixel 0..127
        const int q   = idx & 15;            // channel octet 0..15
        off[it] = p * 16 + q;
        v[it]   = __ldcs(scr16 + off[it]);
    }
    const uint4 z16 = make_uint4(0, 0, 0, 0);
    #pragma unroll
    for (int it = 0; it < 8; it++)
        __stcs(scr16 + off[it], z16);

    if (tid < GT) {
        ovs[tid] = __ldcs(g_oscr + pixbase + tid);
        __stcs(g_oscr + pixbase + tid, 0.f);
    }
    if (tid + 256 < GT + 256 && tid >= 128) { } // (GT==128: covered above)

    // convert + transpose: tile[c][ p ^ ((q&7)<<2) ], c = 8q..8q+7
    #pragma unroll
    for (int it = 0; it < 8; it++) {
        const int p  = off[it] >> 4;
        const int q  = off[it] & 15;
        const int ps = p ^ ((q & 7) << 2);
        const int c0 = q * 8;
        const float2 f0 = __half22float2(*(const __half2*)&v[it].x);
        const float2 f1 = __half22float2(*(const __half2*)&v[it].y);
        const float2 f2 = __half22float2(*(const __half2*)&v[it].z);
        const float2 f3 = __half22float2(*(const __half2*)&v[it].w);
        tile[(c0 + 0) * GPP + ps] = f0.x;
        tile[(c0 + 1) * GPP + ps] = f0.y;
        tile[(c0 + 2) * GPP + ps] = f1.x;
        tile[(c0 + 3) * GPP + ps] = f1.y;
        tile[(c0 + 4) * GPP + ps] = f2.x;
        tile[(c0 + 5) * GPP + ps] = f2.y;
        tile[(c0 + 6) * GPP + ps] = f3.x;
        tile[(c0 + 7) * GPP + ps] = f3.y;
    }
    __syncthreads();

    // ---- phase B: 16 channel-visits per warp, 512B contiguous stores ----
    #pragma unroll
    for (int cb = 0; cb < 16; cb++) {
        const int cl  = cb * 8 + warp;                      // channel 0..127
        const int psw = (lane * 4) ^ (((cl >> 3) & 7) << 2); // swizzle of c's octet
        const float4 vv = *(const float4*)&tile[cl * GPP + psw];
        const float4 ov = *(const float4*)&ovs[lane * 4];
        __stcs((float4*)(out_img_base + (size_t)cl * HW_ + lane * 4), vv);
        __stcs((float4*)(out_o_base   + (size_t)cl * HW_ + lane * 4), ov);
    }
}

extern "C" void kernel_launch(void* const* d_in, const int* in_sizes, int n_in,
                              void* d_out, int out_size)
{
    const float* img;
    const float* flo;
    if (in_sizes[0] == TOTAL_) { img = (const float*)d_in[0]; flo = (const float*)d_in[1]; }
    else                       { img = (const float*)d_in[1]; flo = (const float*)d_in[0]; }
    float* out = (float*)d_out;

    // One-time setup (uncaptured correctness call): R10's teardown-proven
    // footprint — 1 extra stream + 5 events.
    static cudaStream_t s1 = nullptr;
    static cudaEvent_t  evS[N_], evJoin;
    if (s1 == nullptr) {
        cudaStreamCreateWithFlags(&s1, cudaStreamNonBlocking);
        for (int i = 0; i < N_; i++)
            cudaEventCreateWithFlags(&evS[i], cudaEventDisableTiming);
        cudaEventCreateWithFlags(&evJoin, cudaEventDisableTiming);
        cudaFuncSetAttribute(gather_kernel,
                             cudaFuncAttributeMaxDynamicSharedMemorySize, GSMEM);
    }

    // R10 DAG: scatters back-to-back on stream 0; gathers forked onto s1
    // (G_n waits only on S_n).  Join before return.
    for (int n = 0; n < N_; n++) {
        scatter_kernel<<<SCTAS, 256>>>(img, flo, n);
        cudaEventRecord(evS[n], 0);
        cudaStreamWaitEvent(s1, evS[n], 0);
        gather_kernel<<<GCTAS, 256, GSMEM, s1>>>(out, n);
    }
    cudaEventRecord(evJoin, s1);
    cudaStreamWaitEvent(0, evJoin, 0);
}